// round 1
// baseline (speedup 1.0000x reference)
#include <cuda_runtime.h>
#include <cuda_bf16.h>
#include <math.h>

// Problem constants
#define BB   4
#define SS   16384
#define DD   512
#define SEG  256
#define DIL  2
#define LL   128          // SEG / DIL
#define NSEG 64           // SS / SEG
#define TT   (BB * NSEG * LL)   // 32768 dilated tokens

// Scratch for projected Q/K/V (device globals: allocation-guard safe)
static __device__ float g_q[(size_t)TT * DD];
static __device__ float g_k[(size_t)TT * DD];
static __device__ float g_v[(size_t)TT * DD];

// ---------------------------------------------------------------------------
// Phase 1: QKV projection GEMM.
//   out[t, j] = sum_d x_dilated[t, d] * W[j, d] + bias[j]
// M = 32768 (tokens), N = 512, K = 512. blockIdx.z selects Q/K/V.
// BM=128, BN=128, BK=8, 256 threads, 8x8 register tile per thread.
// ---------------------------------------------------------------------------
#define P1_BM 128
#define P1_BN 128
#define P1_BK 8
#define SPAD  132   // padded row stride (floats) to kill smem bank conflicts

__global__ __launch_bounds__(256)
void qkv_proj_kernel(const float* __restrict__ x,
                     const float* __restrict__ Wq, const float* __restrict__ bq,
                     const float* __restrict__ Wk, const float* __restrict__ bk,
                     const float* __restrict__ Wv, const float* __restrict__ bv)
{
    __shared__ float As[P1_BK][SPAD];
    __shared__ float Bs[P1_BK][SPAD];

    const float* W;  const float* bias;  float* out;
    if      (blockIdx.z == 0) { W = Wq; bias = bq; out = g_q; }
    else if (blockIdx.z == 1) { W = Wk; bias = bk; out = g_k; }
    else                      { W = Wv; bias = bv; out = g_v; }

    const int tid = threadIdx.x;
    const int tx  = tid & 15;        // 0..15  -> N direction
    const int ty  = tid >> 4;        // 0..15  -> M direction
    const int m0  = blockIdx.y * P1_BM;
    const int n0  = blockIdx.x * P1_BN;

    // Load assignment: 128 rows x 8 k  (1024 floats per tile, 4 per thread)
    const int lrow = tid >> 1;          // 0..127
    const int lk   = (tid & 1) * 4;     // 0 or 4

    // Map dilated-token index -> row of x
    const int t_a = m0 + lrow;
    const int b_  = t_a >> 13;          // / (NSEG*LL = 8192)
    const int rem = t_a & 8191;
    const int n_  = rem >> 7;           // / LL
    const int l_  = rem & 127;
    const float* arow = x + ((size_t)(b_ * SS + n_ * SEG + l_ * DIL)) * DD;
    const float* brow = W + (size_t)(n0 + lrow) * DD;

    float acc[8][8];
#pragma unroll
    for (int i = 0; i < 8; ++i)
#pragma unroll
        for (int j = 0; j < 8; ++j) acc[i][j] = 0.f;

    for (int k0 = 0; k0 < DD; k0 += P1_BK) {
        float4 a4 = *(const float4*)(arow + k0 + lk);
        float4 b4 = *(const float4*)(brow + k0 + lk);
        __syncthreads();
        As[lk + 0][lrow] = a4.x; As[lk + 1][lrow] = a4.y;
        As[lk + 2][lrow] = a4.z; As[lk + 3][lrow] = a4.w;
        Bs[lk + 0][lrow] = b4.x; Bs[lk + 1][lrow] = b4.y;
        Bs[lk + 2][lrow] = b4.z; Bs[lk + 3][lrow] = b4.w;
        __syncthreads();
#pragma unroll
        for (int k = 0; k < P1_BK; ++k) {
            float4 a0 = *(const float4*)&As[k][ty * 8];
            float4 a1 = *(const float4*)&As[k][ty * 8 + 4];
            float4 b0 = *(const float4*)&Bs[k][tx * 8];
            float4 b1 = *(const float4*)&Bs[k][tx * 8 + 4];
            float ar[8] = {a0.x, a0.y, a0.z, a0.w, a1.x, a1.y, a1.z, a1.w};
            float br[8] = {b0.x, b0.y, b0.z, b0.w, b1.x, b1.y, b1.z, b1.w};
#pragma unroll
            for (int i = 0; i < 8; ++i)
#pragma unroll
                for (int j = 0; j < 8; ++j)
                    acc[i][j] = fmaf(ar[i], br[j], acc[i][j]);
        }
    }

    // Epilogue: add bias, store
    float bv0[8];
#pragma unroll
    for (int j = 0; j < 8; ++j) bv0[j] = bias[n0 + tx * 8 + j];

#pragma unroll
    for (int i = 0; i < 8; ++i) {
        float* orow = out + (size_t)(m0 + ty * 8 + i) * DD + n0 + tx * 8;
        float4 o0 = make_float4(acc[i][0] + bv0[0], acc[i][1] + bv0[1],
                                acc[i][2] + bv0[2], acc[i][3] + bv0[3]);
        float4 o1 = make_float4(acc[i][4] + bv0[4], acc[i][5] + bv0[5],
                                acc[i][6] + bv0[6], acc[i][7] + bv0[7]);
        *(float4*)(orow + 0) = o0;
        *(float4*)(orow + 4) = o1;
    }
}

// ---------------------------------------------------------------------------
// Phase 2: per-segment attention. One CTA per segment (256 segments).
//   scores = (Q @ K^T) * scale  -> softmax rows -> O = attn @ V
// Dynamic smem: scores[128][132] + tile region (Qs/Ks, reused for Vs).
// ---------------------------------------------------------------------------
#define A_BK 8
#define ATTN_SMEM_FLOATS (128 * SPAD + 2 * A_BK * SPAD)
#define ATTN_SMEM_BYTES  (ATTN_SMEM_FLOATS * 4)

__global__ __launch_bounds__(256)
void attn_kernel(float* __restrict__ out)
{
    extern __shared__ float sm[];
    float* sc   = sm;                  // 128 x SPAD  (scores / attn)
    float* tQ   = sm + 128 * SPAD;     // A_BK x SPAD
    float* tK   = tQ + A_BK * SPAD;    // A_BK x SPAD
    float* tV   = tQ;                  // reused in step 3

    const int seg = blockIdx.x;        // 0..255
    const int t0  = seg * LL;          // first token of this segment
    const int tid = threadIdx.x;
    const int tx  = tid & 15;
    const int ty  = tid >> 4;
    const int lrow = tid >> 1;
    const int lk   = (tid & 1) * 4;

    const float scale = 0.044194173824159216f;  // 1/sqrt(512)

    // ---- Step 1: scores = Q @ K^T * scale ----
    {
        const float* qrow = g_q + (size_t)(t0 + lrow) * DD;
        const float* krow = g_k + (size_t)(t0 + lrow) * DD;
        float acc[8][8];
#pragma unroll
        for (int i = 0; i < 8; ++i)
#pragma unroll
            for (int j = 0; j < 8; ++j) acc[i][j] = 0.f;

        for (int k0 = 0; k0 < DD; k0 += A_BK) {
            float4 a4 = *(const float4*)(qrow + k0 + lk);
            float4 b4 = *(const float4*)(krow + k0 + lk);
            __syncthreads();
            tQ[(lk + 0) * SPAD + lrow] = a4.x; tQ[(lk + 1) * SPAD + lrow] = a4.y;
            tQ[(lk + 2) * SPAD + lrow] = a4.z; tQ[(lk + 3) * SPAD + lrow] = a4.w;
            tK[(lk + 0) * SPAD + lrow] = b4.x; tK[(lk + 1) * SPAD + lrow] = b4.y;
            tK[(lk + 2) * SPAD + lrow] = b4.z; tK[(lk + 3) * SPAD + lrow] = b4.w;
            __syncthreads();
#pragma unroll
            for (int k = 0; k < A_BK; ++k) {
                float4 a0 = *(const float4*)&tQ[k * SPAD + ty * 8];
                float4 a1 = *(const float4*)&tQ[k * SPAD + ty * 8 + 4];
                float4 b0 = *(const float4*)&tK[k * SPAD + tx * 8];
                float4 b1 = *(const float4*)&tK[k * SPAD + tx * 8 + 4];
                float ar[8] = {a0.x, a0.y, a0.z, a0.w, a1.x, a1.y, a1.z, a1.w};
                float br[8] = {b0.x, b0.y, b0.z, b0.w, b1.x, b1.y, b1.z, b1.w};
#pragma unroll
                for (int i = 0; i < 8; ++i)
#pragma unroll
                    for (int j = 0; j < 8; ++j)
                        acc[i][j] = fmaf(ar[i], br[j], acc[i][j]);
            }
        }
        __syncthreads();
#pragma unroll
        for (int i = 0; i < 8; ++i)
#pragma unroll
            for (int j = 0; j < 8; ++j)
                sc[(ty * 8 + i) * SPAD + tx * 8 + j] = acc[i][j] * scale;
        __syncthreads();
    }

    // ---- Step 2: row softmax over sc (128 rows x 128 cols) ----
    {
        const int warp = tid >> 5;
        const int lane = tid & 31;
        for (int r = warp * 16; r < warp * 16 + 16; ++r) {
            float4 v = *(float4*)&sc[r * SPAD + lane * 4];
            float mx = fmaxf(fmaxf(v.x, v.y), fmaxf(v.z, v.w));
#pragma unroll
            for (int off = 16; off >= 1; off >>= 1)
                mx = fmaxf(mx, __shfl_xor_sync(0xFFFFFFFFu, mx, off));
            float4 e;
            e.x = __expf(v.x - mx); e.y = __expf(v.y - mx);
            e.z = __expf(v.z - mx); e.w = __expf(v.w - mx);
            float s = e.x + e.y + e.z + e.w;
#pragma unroll
            for (int off = 16; off >= 1; off >>= 1)
                s += __shfl_xor_sync(0xFFFFFFFFu, s, off);
            float inv = 1.0f / s;
            e.x *= inv; e.y *= inv; e.z *= inv; e.w *= inv;
            *(float4*)&sc[r * SPAD + lane * 4] = e;
        }
        __syncthreads();
    }

    // ---- Step 3: O = attn @ V, tiled over 4 chunks of 128 output cols ----
    {
        const int vrow = tid >> 5;          // 0..7
        const int vcol = (tid & 31) * 4;    // 0..124
        for (int nc = 0; nc < DD; nc += 128) {
            float acc[8][8];
#pragma unroll
            for (int i = 0; i < 8; ++i)
#pragma unroll
                for (int j = 0; j < 8; ++j) acc[i][j] = 0.f;

            for (int k0 = 0; k0 < LL; k0 += A_BK) {
                float4 v4 = *(const float4*)(g_v + (size_t)(t0 + k0 + vrow) * DD + nc + vcol);
                __syncthreads();
                *(float4*)&tV[vrow * SPAD + vcol] = v4;
                __syncthreads();
#pragma unroll
                for (int k = 0; k < A_BK; ++k) {
                    float ar[8];
#pragma unroll
                    for (int i = 0; i < 8; ++i)
                        ar[i] = sc[(ty * 8 + i) * SPAD + k0 + k];
                    float4 b0 = *(const float4*)&tV[k * SPAD + tx * 8];
                    float4 b1 = *(const float4*)&tV[k * SPAD + tx * 8 + 4];
                    float br[8] = {b0.x, b0.y, b0.z, b0.w, b1.x, b1.y, b1.z, b1.w};
#pragma unroll
                    for (int i = 0; i < 8; ++i)
#pragma unroll
                        for (int j = 0; j < 8; ++j)
                            acc[i][j] = fmaf(ar[i], br[j], acc[i][j]);
                }
            }

#pragma unroll
            for (int i = 0; i < 8; ++i) {
                float* orow = out + (size_t)(t0 + ty * 8 + i) * DD + nc + tx * 8;
                float4 o0 = make_float4(acc[i][0], acc[i][1], acc[i][2], acc[i][3]);
                float4 o1 = make_float4(acc[i][4], acc[i][5], acc[i][6], acc[i][7]);
                *(float4*)(orow + 0) = o0;
                *(float4*)(orow + 4) = o1;
            }
            __syncthreads();  // protect tV before next chunk overwrite
        }
    }
}

// ---------------------------------------------------------------------------
// Launch
// ---------------------------------------------------------------------------
extern "C" void kernel_launch(void* const* d_in, const int* in_sizes, int n_in,
                              void* d_out, int out_size)
{
    const float* x  = (const float*)d_in[0];
    const float* Wq = (const float*)d_in[1];
    const float* bq = (const float*)d_in[2];
    const float* Wk = (const float*)d_in[3];
    const float* bk = (const float*)d_in[4];
    const float* Wv = (const float*)d_in[5];
    const float* bv = (const float*)d_in[6];
    float* out = (float*)d_out;

    // Opt-in to >48KB dynamic smem for the attention kernel (idempotent,
    // not a stream-ordered op — safe under graph capture).
    cudaFuncSetAttribute(attn_kernel,
                         cudaFuncAttributeMaxDynamicSharedMemorySize,
                         ATTN_SMEM_BYTES);

    // Phase 1: QKV projection. Grid: N-tiles x M-tiles x {Q,K,V}
    dim3 g1(DD / P1_BN, TT / P1_BM, 3);
    qkv_proj_kernel<<<g1, 256>>>(x, Wq, bq, Wk, bk, Wv, bv);

    // Phase 2: per-segment attention
    attn_kernel<<<BB * NSEG, 256, ATTN_SMEM_BYTES>>>(out);
}

// round 3
// speedup vs baseline: 2.4397x; 2.4397x over previous
#include <cuda_runtime.h>
#include <cuda_bf16.h>
#include <math.h>
#include <cstdint>

// Problem constants
#define BB   4
#define SS   16384
#define DD   512
#define SEG  256
#define LL   128          // SEG / DIL
#define NSEG 64           // SS / SEG
#define TT   (BB * NSEG * LL)   // 32768 dilated tokens

// Scratch for projected Q/K/V
static __device__ float g_q[(size_t)TT * DD];
static __device__ float g_k[(size_t)TT * DD];
static __device__ float g_v[(size_t)TT * DD];

// ---------------------------------------------------------------------------
// tf32 warp MMA helpers (sm_80+ PTX, no arch-specific 'a' features needed)
// ---------------------------------------------------------------------------
__device__ __forceinline__ uint32_t f2tf32(float f) {
    uint32_t u;
    asm("cvt.rna.tf32.f32 %0, %1;" : "=r"(u) : "f"(f));
    return u;
}

// D(16x8) += A(16x8) * B(8x8);  A row-major frag, B col-major frag.
__device__ __forceinline__ void mma_tf32(float d[4], const uint32_t a[4],
                                         const uint32_t b[2]) {
    asm volatile(
        "mma.sync.aligned.m16n8k8.row.col.f32.tf32.tf32.f32 "
        "{%0,%1,%2,%3}, {%4,%5,%6,%7}, {%8,%9}, {%0,%1,%2,%3};\n"
        : "+f"(d[0]), "+f"(d[1]), "+f"(d[2]), "+f"(d[3])
        : "r"(a[0]), "r"(a[1]), "r"(a[2]), "r"(a[3]), "r"(b[0]), "r"(b[1]));
}

// ---------------------------------------------------------------------------
// Phase 1: QKV projection.  out[t,j] = sum_d x_dil[t,d] * W[j,d] + b[j]
// CTA 128Mx128N, BK=32, 256 threads = 8 warps (4Mx2N), warp tile 32x64.
// SMEM strides of 36 words make all fragment loads bank-conflict-free:
//   bank(addr) = (4*row + k) mod 32, distinct for row<8, k<4.
// ---------------------------------------------------------------------------
#define P1_BK  32
#define P1_ST  36

__global__ __launch_bounds__(256)
void qkv_tc(const float* __restrict__ x,
            const float* __restrict__ Wq, const float* __restrict__ bq,
            const float* __restrict__ Wk, const float* __restrict__ bk,
            const float* __restrict__ Wv, const float* __restrict__ bv)
{
    __shared__ uint32_t sA[128][P1_ST];
    __shared__ uint32_t sB[128][P1_ST];

    const float* W; const float* bias; float* out;
    if      (blockIdx.z == 0) { W = Wq; bias = bq; out = g_q; }
    else if (blockIdx.z == 1) { W = Wk; bias = bk; out = g_k; }
    else                      { W = Wv; bias = bv; out = g_v; }

    const int tid  = threadIdx.x;
    const int lane = tid & 31;
    const int wid  = tid >> 5;
    const int wm   = wid >> 1;        // 0..3 -> M offset 32*wm
    const int wn   = wid & 1;         // 0..1 -> N offset 64*wn
    const int m0   = blockIdx.y * 128;
    const int n0   = blockIdx.x * 128;

    // Staging: thread loads 16 A floats + 16 B floats per iter
    const int lrow = tid >> 1;            // 0..127
    const int lk   = (tid & 1) * 16;      // 0 or 16

    // dilated-token address for A row
    const int tg = m0 + lrow;
    const int b_ = tg >> 13;
    const int n_ = (tg >> 7) & 63;
    const int l_ = tg & 127;
    const float* arow = x + ((size_t)(b_ * SS + n_ * SEG + l_ * 2)) * DD;
    const float* brow = W + (size_t)(n0 + lrow) * DD;

    float acc[2][8][4];
#pragma unroll
    for (int i = 0; i < 2; ++i)
#pragma unroll
        for (int j = 0; j < 8; ++j)
#pragma unroll
            for (int q = 0; q < 4; ++q) acc[i][j][q] = 0.f;

    float4 pa[4], pb[4];
#pragma unroll
    for (int j = 0; j < 4; ++j) {
        pa[j] = *(const float4*)(arow + lk + 4 * j);
        pb[j] = *(const float4*)(brow + lk + 4 * j);
    }

    const int r = lane >> 2;
    const int c = lane & 3;

    for (int it = 0; it < DD / P1_BK; ++it) {
        __syncthreads();
#pragma unroll
        for (int j = 0; j < 4; ++j) {
            uint4 ua = make_uint4(f2tf32(pa[j].x), f2tf32(pa[j].y),
                                  f2tf32(pa[j].z), f2tf32(pa[j].w));
            uint4 ub = make_uint4(f2tf32(pb[j].x), f2tf32(pb[j].y),
                                  f2tf32(pb[j].z), f2tf32(pb[j].w));
            *(uint4*)&sA[lrow][lk + 4 * j] = ua;
            *(uint4*)&sB[lrow][lk + 4 * j] = ub;
        }
        __syncthreads();
        if (it + 1 < DD / P1_BK) {
            const float* an = arow + (it + 1) * P1_BK;
            const float* bn = brow + (it + 1) * P1_BK;
#pragma unroll
            for (int j = 0; j < 4; ++j) {
                pa[j] = *(const float4*)(an + lk + 4 * j);
                pb[j] = *(const float4*)(bn + lk + 4 * j);
            }
        }
#pragma unroll
        for (int kk = 0; kk < P1_BK; kk += 8) {
            uint32_t af[2][4], bf[8][2];
#pragma unroll
            for (int mt = 0; mt < 2; ++mt) {
                const int m = wm * 32 + mt * 16 + r;
                af[mt][0] = sA[m][kk + c];
                af[mt][1] = sA[m + 8][kk + c];
                af[mt][2] = sA[m][kk + c + 4];
                af[mt][3] = sA[m + 8][kk + c + 4];
            }
#pragma unroll
            for (int nt = 0; nt < 8; ++nt) {
                const int n = wn * 64 + nt * 8 + r;
                bf[nt][0] = sB[n][kk + c];
                bf[nt][1] = sB[n][kk + c + 4];
            }
#pragma unroll
            for (int mt = 0; mt < 2; ++mt)
#pragma unroll
                for (int nt = 0; nt < 8; ++nt)
                    mma_tf32(acc[mt][nt], af[mt], bf[nt]);
        }
    }

    // Epilogue: bias add, fragment-mapped float2 stores
#pragma unroll
    for (int mt = 0; mt < 2; ++mt) {
#pragma unroll
        for (int nt = 0; nt < 8; ++nt) {
            const int row = m0 + wm * 32 + mt * 16 + r;
            const int col = n0 + wn * 64 + nt * 8 + 2 * c;
            const float b0 = bias[col], b1 = bias[col + 1];
            *(float2*)(out + (size_t)row * DD + col) =
                make_float2(acc[mt][nt][0] + b0, acc[mt][nt][1] + b1);
            *(float2*)(out + (size_t)(row + 8) * DD + col) =
                make_float2(acc[mt][nt][2] + b0, acc[mt][nt][3] + b1);
        }
    }
}

// ---------------------------------------------------------------------------
// Phase 2: per-segment attention (256 CTAs, 256 threads).
//   scores = (Q K^T)*scale -> softmax -> O = attn V
// All GEMMs via tf32 mma.sync.  sc stride 132 and V stride 136 are
// conflict-free for the fragment access patterns.
// ---------------------------------------------------------------------------
#define SC_ST 132
#define QK_ST 36
#define V_ST  136
#define ATTN_SMEM_BYTES ((128 * SC_ST + 2 * 128 * QK_ST) * 4)   // 104448

__global__ __launch_bounds__(256)
void attn_tc(float* __restrict__ out)
{
    extern __shared__ float sm[];
    float*    sc = sm;                                   // 128 x 132
    uint32_t* sQ = (uint32_t*)(sm + 128 * SC_ST);        // 128 x 36
    uint32_t* sK = sQ + 128 * QK_ST;                     // 128 x 36
    uint32_t* sV = sQ;                                   // 32 x 136 (reuse)

    const int seg = blockIdx.x;
    const int t0  = seg * LL;
    const int tid = threadIdx.x;
    const int lane = tid & 31;
    const int wid  = tid >> 5;
    const int wm   = wid >> 1;
    const int wn   = wid & 1;
    const int r    = lane >> 2;
    const int c    = lane & 3;

    const float scale = 0.044194173824159216f;  // 1/sqrt(512)

    // ============ Step 1: scores = Q K^T * scale ============
    {
        const int lrow = tid >> 1;
        const int lk   = (tid & 1) * 16;
        const float* qrow = g_q + (size_t)(t0 + lrow) * DD;
        const float* krow = g_k + (size_t)(t0 + lrow) * DD;

        float acc[2][8][4];
#pragma unroll
        for (int i = 0; i < 2; ++i)
#pragma unroll
            for (int j = 0; j < 8; ++j)
#pragma unroll
                for (int q = 0; q < 4; ++q) acc[i][j][q] = 0.f;

        float4 pa[4], pb[4];
#pragma unroll
        for (int j = 0; j < 4; ++j) {
            pa[j] = *(const float4*)(qrow + lk + 4 * j);
            pb[j] = *(const float4*)(krow + lk + 4 * j);
        }

        for (int it = 0; it < DD / 32; ++it) {
            __syncthreads();
#pragma unroll
            for (int j = 0; j < 4; ++j) {
                uint4 ua = make_uint4(f2tf32(pa[j].x), f2tf32(pa[j].y),
                                      f2tf32(pa[j].z), f2tf32(pa[j].w));
                uint4 ub = make_uint4(f2tf32(pb[j].x), f2tf32(pb[j].y),
                                      f2tf32(pb[j].z), f2tf32(pb[j].w));
                *(uint4*)&sQ[lrow * QK_ST + lk + 4 * j] = ua;
                *(uint4*)&sK[lrow * QK_ST + lk + 4 * j] = ub;
            }
            __syncthreads();
            if (it + 1 < DD / 32) {
                const float* qn = qrow + (it + 1) * 32;
                const float* kn = krow + (it + 1) * 32;
#pragma unroll
                for (int j = 0; j < 4; ++j) {
                    pa[j] = *(const float4*)(qn + lk + 4 * j);
                    pb[j] = *(const float4*)(kn + lk + 4 * j);
                }
            }
#pragma unroll
            for (int kk = 0; kk < 32; kk += 8) {
                uint32_t af[2][4], bf[8][2];
#pragma unroll
                for (int mt = 0; mt < 2; ++mt) {
                    const int m = wm * 32 + mt * 16 + r;
                    af[mt][0] = sQ[m * QK_ST + kk + c];
                    af[mt][1] = sQ[(m + 8) * QK_ST + kk + c];
                    af[mt][2] = sQ[m * QK_ST + kk + c + 4];
                    af[mt][3] = sQ[(m + 8) * QK_ST + kk + c + 4];
                }
#pragma unroll
                for (int nt = 0; nt < 8; ++nt) {
                    const int n = wn * 64 + nt * 8 + r;
                    bf[nt][0] = sK[n * QK_ST + kk + c];
                    bf[nt][1] = sK[n * QK_ST + kk + c + 4];
                }
#pragma unroll
                for (int mt = 0; mt < 2; ++mt)
#pragma unroll
                    for (int nt = 0; nt < 8; ++nt)
                        mma_tf32(acc[mt][nt], af[mt], bf[nt]);
            }
        }
        __syncthreads();
        // write scaled scores into sc (fp32)
#pragma unroll
        for (int mt = 0; mt < 2; ++mt)
#pragma unroll
            for (int nt = 0; nt < 8; ++nt) {
                const int row = wm * 32 + mt * 16 + r;
                const int col = wn * 64 + nt * 8 + 2 * c;
                *(float2*)&sc[row * SC_ST + col] =
                    make_float2(acc[mt][nt][0] * scale, acc[mt][nt][1] * scale);
                *(float2*)&sc[(row + 8) * SC_ST + col] =
                    make_float2(acc[mt][nt][2] * scale, acc[mt][nt][3] * scale);
            }
        __syncthreads();
    }

    // ============ Step 2: row softmax (write back tf32-rounded) ============
    {
        for (int row = wid * 16; row < wid * 16 + 16; ++row) {
            float4 v = *(float4*)&sc[row * SC_ST + lane * 4];
            float mx = fmaxf(fmaxf(v.x, v.y), fmaxf(v.z, v.w));
#pragma unroll
            for (int off = 16; off >= 1; off >>= 1)
                mx = fmaxf(mx, __shfl_xor_sync(0xFFFFFFFFu, mx, off));
            float4 e;
            e.x = __expf(v.x - mx); e.y = __expf(v.y - mx);
            e.z = __expf(v.z - mx); e.w = __expf(v.w - mx);
            float s = e.x + e.y + e.z + e.w;
#pragma unroll
            for (int off = 16; off >= 1; off >>= 1)
                s += __shfl_xor_sync(0xFFFFFFFFu, s, off);
            const float inv = 1.0f / s;
            uint4 u = make_uint4(f2tf32(e.x * inv), f2tf32(e.y * inv),
                                 f2tf32(e.z * inv), f2tf32(e.w * inv));
            *(uint4*)&sc[row * SC_ST + lane * 4] = u;
        }
        __syncthreads();
    }

    // ============ Step 3: O = attn V  (N in 4 chunks of 128) ============
    {
        const uint32_t* scu = (const uint32_t*)sc;
        const int vrow = tid >> 3;           // 0..31
        const int vcol = (tid & 7) * 16;     // 0..112

        for (int dc = 0; dc < DD; dc += 128) {
            float acc[2][8][4];
#pragma unroll
            for (int i = 0; i < 2; ++i)
#pragma unroll
                for (int j = 0; j < 8; ++j)
#pragma unroll
                    for (int q = 0; q < 4; ++q) acc[i][j][q] = 0.f;

            for (int k0 = 0; k0 < LL; k0 += 32) {
                __syncthreads();
                // stage V[k0..k0+32) x [dc..dc+128) -> sV[32][136]
                const float* vr = g_v + (size_t)(t0 + k0 + vrow) * DD + dc + vcol;
#pragma unroll
                for (int j = 0; j < 4; ++j) {
                    float4 v4 = *(const float4*)(vr + 4 * j);
                    uint4 u = make_uint4(f2tf32(v4.x), f2tf32(v4.y),
                                         f2tf32(v4.z), f2tf32(v4.w));
                    *(uint4*)&sV[vrow * V_ST + vcol + 4 * j] = u;
                }
                __syncthreads();
#pragma unroll
                for (int kk = 0; kk < 32; kk += 8) {
                    uint32_t af[2][4], bf[8][2];
#pragma unroll
                    for (int mt = 0; mt < 2; ++mt) {
                        const int m = wm * 32 + mt * 16 + r;
                        const int kb = k0 + kk + c;
                        af[mt][0] = scu[m * SC_ST + kb];
                        af[mt][1] = scu[(m + 8) * SC_ST + kb];
                        af[mt][2] = scu[m * SC_ST + kb + 4];
                        af[mt][3] = scu[(m + 8) * SC_ST + kb + 4];
                    }
#pragma unroll
                    for (int nt = 0; nt < 8; ++nt) {
                        const int n = wn * 64 + nt * 8 + r;
                        bf[nt][0] = sV[(kk + c) * V_ST + n];
                        bf[nt][1] = sV[(kk + c + 4) * V_ST + n];
                    }
#pragma unroll
                    for (int mt = 0; mt < 2; ++mt)
#pragma unroll
                        for (int nt = 0; nt < 8; ++nt)
                            mma_tf32(acc[mt][nt], af[mt], bf[nt]);
                }
            }

            // store output chunk
#pragma unroll
            for (int mt = 0; mt < 2; ++mt)
#pragma unroll
                for (int nt = 0; nt < 8; ++nt) {
                    const int row = t0 + wm * 32 + mt * 16 + r;
                    const int col = dc + wn * 64 + nt * 8 + 2 * c;
                    *(float2*)(out + (size_t)row * DD + col) =
                        make_float2(acc[mt][nt][0], acc[mt][nt][1]);
                    *(float2*)(out + (size_t)(row + 8) * DD + col) =
                        make_float2(acc[mt][nt][2], acc[mt][nt][3]);
                }
        }
    }
}

// ---------------------------------------------------------------------------
// Launch
// ---------------------------------------------------------------------------
extern "C" void kernel_launch(void* const* d_in, const int* in_sizes, int n_in,
                              void* d_out, int out_size)
{
    const float* x  = (const float*)d_in[0];
    const float* Wq = (const float*)d_in[1];
    const float* bq = (const float*)d_in[2];
    const float* Wk = (const float*)d_in[3];
    const float* bk = (const float*)d_in[4];
    const float* Wv = (const float*)d_in[5];
    const float* bv = (const float*)d_in[6];
    float* out = (float*)d_out;

    cudaFuncSetAttribute(attn_tc,
                         cudaFuncAttributeMaxDynamicSharedMemorySize,
                         ATTN_SMEM_BYTES);

    // Phase 1: QKV projection (tensor path). Grid: N-tiles x M-tiles x {Q,K,V}
    dim3 g1(DD / 128, TT / 128, 3);
    qkv_tc<<<g1, 256>>>(x, Wq, bq, Wk, bk, Wv, bv);

    // Phase 2: per-segment attention
    attn_tc<<<BB * NSEG, 256, ATTN_SMEM_BYTES>>>(out);
}

// round 4
// speedup vs baseline: 2.4540x; 1.0058x over previous
#include <cuda_runtime.h>
#include <math.h>
#include <cstdint>

// Problem constants
#define BB   4
#define SS   16384
#define DD   512
#define SEG  256
#define LL   128
#define NSEG 64
#define TT   (BB * NSEG * LL)   // 32768 dilated tokens

// Device scratch (allocation-guard safe)
static __device__ float g_xd[(size_t)TT * DD];       // dilated x, tf32-rounded
static __device__ float g_w[3 * DD * DD];            // Wq|Wk|Wv, tf32-rounded
static __device__ float g_q[(size_t)TT * DD];
static __device__ float g_k[(size_t)TT * DD];
static __device__ float g_v[(size_t)TT * DD];

// ---------------------------------------------------------------------------
// Helpers
// ---------------------------------------------------------------------------
__device__ __forceinline__ uint32_t f2tf32(float f) {
    uint32_t u;
    asm("cvt.rna.tf32.f32 %0, %1;" : "=r"(u) : "f"(f));
    return u;
}
__device__ __forceinline__ void mma_tf32(float d[4], const uint32_t a[4],
                                         const uint32_t b[2]) {
    asm volatile(
        "mma.sync.aligned.m16n8k8.row.col.f32.tf32.tf32.f32 "
        "{%0,%1,%2,%3}, {%4,%5,%6,%7}, {%8,%9}, {%0,%1,%2,%3};\n"
        : "+f"(d[0]), "+f"(d[1]), "+f"(d[2]), "+f"(d[3])
        : "r"(a[0]), "r"(a[1]), "r"(a[2]), "r"(a[3]), "r"(b[0]), "r"(b[1]));
}
__device__ __forceinline__ uint32_t smem_u32(const void* p) {
    uint32_t a;
    asm("{ .reg .u64 t; cvta.to.shared.u64 t, %1; cvt.u32.u64 %0, t; }"
        : "=r"(a) : "l"(p));
    return a;
}
__device__ __forceinline__ void cp16(uint32_t dst, const void* src) {
    asm volatile("cp.async.cg.shared.global [%0], [%1], 16;"
                 :: "r"(dst), "l"(src));
}
__device__ __forceinline__ void cp_commit() {
    asm volatile("cp.async.commit_group;" ::: "memory");
}
__device__ __forceinline__ void cp_wait0() {
    asm volatile("cp.async.wait_group 0;" ::: "memory");
}

// ---------------------------------------------------------------------------
// Prep: gather dilated rows of x and round x, W to tf32 (removes all cvt
// from GEMM hot loops; numerically identical to rounding at stage time).
// ---------------------------------------------------------------------------
__global__ __launch_bounds__(256)
void prep_kernel(const float* __restrict__ x,
                 const float* __restrict__ Wq,
                 const float* __restrict__ Wk,
                 const float* __restrict__ Wv)
{
    const size_t qi = (size_t)blockIdx.x * blockDim.x + threadIdx.x;
    const size_t XQ = (size_t)TT * DD / 4;        // 4,194,304 quads
    if (qi < XQ) {
        const int t = (int)(qi >> 7);
        const int d = ((int)qi & 127) << 2;
        const int b_ = t >> 13, n_ = (t >> 7) & 63, l_ = t & 127;
        float4 v = *(const float4*)(x + ((size_t)(b_ * SS + n_ * SEG + l_ * 2)) * DD + d);
        uint4 u = make_uint4(f2tf32(v.x), f2tf32(v.y), f2tf32(v.z), f2tf32(v.w));
        *(uint4*)(g_xd + (size_t)t * DD + d) = u;
    } else {
        const size_t wi = qi - XQ;
        if (wi < (size_t)3 * DD * DD / 4) {
            const int m = (int)(wi >> 16);
            const float* W = (m == 0) ? Wq : ((m == 1) ? Wk : Wv);
            const int off = ((int)wi & 65535) << 2;
            float4 v = *(const float4*)(W + off);
            uint4 u = make_uint4(f2tf32(v.x), f2tf32(v.y), f2tf32(v.z), f2tf32(v.w));
            *(uint4*)(g_w + (size_t)m * DD * DD + off) = u;
        }
    }
}

// ---------------------------------------------------------------------------
// QKV projection: 128M x 128N tiles, BK=32, cp.async double-buffered,
// one __syncthreads per K-iter. 8 warps (4M x 2N), warp tile 32x64.
// Stride-36 SMEM rows: fragment loads conflict-free.
// ---------------------------------------------------------------------------
#define ST   36
#define BUFW (128 * ST)
#define QKV_SMEM_BYTES (4 * BUFW * 4)   // 73728

__global__ __launch_bounds__(256, 2)
void qkv_tc(const float* __restrict__ bq, const float* __restrict__ bk,
            const float* __restrict__ bv)
{
    extern __shared__ uint32_t smw[];
    const int tid = threadIdx.x;
    const int lane = tid & 31, wid = tid >> 5;
    const int wm = wid >> 1, wn = wid & 1;
    const int r = lane >> 2, c = lane & 3;
    const int m0 = blockIdx.y * 128, n0 = blockIdx.x * 128, z = blockIdx.z;

    const float* A  = g_xd + (size_t)m0 * DD;
    const float* Bm = g_w + (size_t)z * DD * DD + (size_t)n0 * DD;
    const float* bias = (z == 0) ? bq : ((z == 1) ? bk : bv);
    float* out = (z == 0) ? g_q : ((z == 1) ? g_k : g_v);

    const int row = tid >> 1, lk = (tid & 1) * 16;
    const char* gA = (const char*)(A + (size_t)row * DD + lk);
    const char* gB = (const char*)(Bm + (size_t)row * DD + lk);
    const uint32_t sb = smem_u32(smw);
    const uint32_t so = (row * ST + lk) * 4;

    float acc[2][8][4];
#pragma unroll
    for (int i = 0; i < 2; ++i)
#pragma unroll
        for (int j = 0; j < 8; ++j)
#pragma unroll
            for (int q = 0; q < 4; ++q) acc[i][j][q] = 0.f;

#define QKV_STAGE(buf, it) do { \
    uint32_t ba = sb + (buf) * 2 * BUFW * 4; \
    uint32_t bb = ba + BUFW * 4; \
    const char* pa = gA + (it) * 128; \
    const char* pb = gB + (it) * 128; \
    _Pragma("unroll") \
    for (int j = 0; j < 4; ++j) { \
        cp16(ba + so + 16 * j, pa + 16 * j); \
        cp16(bb + so + 16 * j, pb + 16 * j); \
    } \
    cp_commit(); \
} while (0)

    QKV_STAGE(0, 0);
    for (int it = 0; it < 16; ++it) {
        const int buf = it & 1;
        cp_wait0();
        __syncthreads();
        if (it + 1 < 16) QKV_STAGE(buf ^ 1, it + 1);
        const uint32_t* bA = smw + buf * 2 * BUFW;
        const uint32_t* bB = bA + BUFW;
#pragma unroll
        for (int kk = 0; kk < 32; kk += 8) {
            uint32_t af[2][4], bf[8][2];
#pragma unroll
            for (int mt = 0; mt < 2; ++mt) {
                const int m = wm * 32 + mt * 16 + r;
                af[mt][0] = bA[m * ST + kk + c];
                af[mt][1] = bA[(m + 8) * ST + kk + c];
                af[mt][2] = bA[m * ST + kk + c + 4];
                af[mt][3] = bA[(m + 8) * ST + kk + c + 4];
            }
#pragma unroll
            for (int nt = 0; nt < 8; ++nt) {
                const int n = wn * 64 + nt * 8 + r;
                bf[nt][0] = bB[n * ST + kk + c];
                bf[nt][1] = bB[n * ST + kk + c + 4];
            }
#pragma unroll
            for (int mt = 0; mt < 2; ++mt)
#pragma unroll
                for (int nt = 0; nt < 8; ++nt)
                    mma_tf32(acc[mt][nt], af[mt], bf[nt]);
        }
    }

    // Epilogue: bias add, round to tf32 (consumed as tf32 downstream)
#pragma unroll
    for (int mt = 0; mt < 2; ++mt)
#pragma unroll
        for (int nt = 0; nt < 8; ++nt) {
            const int orow = m0 + wm * 32 + mt * 16 + r;
            const int col = n0 + wn * 64 + nt * 8 + 2 * c;
            const float b0 = bias[col], b1 = bias[col + 1];
            float2 o0, o1;
            o0.x = __uint_as_float(f2tf32(acc[mt][nt][0] + b0));
            o0.y = __uint_as_float(f2tf32(acc[mt][nt][1] + b1));
            o1.x = __uint_as_float(f2tf32(acc[mt][nt][2] + b0));
            o1.y = __uint_as_float(f2tf32(acc[mt][nt][3] + b1));
            *(float2*)(out + (size_t)orow * DD + col) = o0;
            *(float2*)(out + (size_t)(orow + 8) * DD + col) = o1;
        }
}

// ---------------------------------------------------------------------------
// Attention: one CTA per segment. cp.async double-buffered QK and V staging.
// SMEM: sc[128][132] fp32 + QK/V region (4 * 128 * 36 words).
// ---------------------------------------------------------------------------
#define SC_ST 132
#define V_ST  136
#define ATTN_QK_WORDS (4 * 128 * ST)
#define ATTN_SMEM_BYTES ((128 * SC_ST + ATTN_QK_WORDS) * 4)   // 141312

__global__ __launch_bounds__(256, 1)
void attn_tc(float* __restrict__ out)
{
    extern __shared__ float sm[];
    float*    sc  = sm;                               // 128 x 132 fp32
    uint32_t* qkb = (uint32_t*)(sm + 128 * SC_ST);    // staging region

    const int seg = blockIdx.x;
    const int t0  = seg * LL;
    const int tid = threadIdx.x;
    const int lane = tid & 31, wid = tid >> 5;
    const int wm = wid >> 1, wn = wid & 1;
    const int r = lane >> 2, c = lane & 3;
    const float scale = 0.044194173824159216f;   // 1/sqrt(512)

    // ============ Step 1: scores = Q K^T * scale ============
    {
        const int row = tid >> 1, lk = (tid & 1) * 16;
        const char* gQ = (const char*)(g_q + (size_t)(t0 + row) * DD + lk);
        const char* gK = (const char*)(g_k + (size_t)(t0 + row) * DD + lk);
        const uint32_t sb = smem_u32(qkb);
        const uint32_t so = (row * ST + lk) * 4;

        float acc[2][8][4];
#pragma unroll
        for (int i = 0; i < 2; ++i)
#pragma unroll
            for (int j = 0; j < 8; ++j)
#pragma unroll
                for (int q = 0; q < 4; ++q) acc[i][j][q] = 0.f;

#define QK_STAGE(buf, it) do { \
    uint32_t ba = sb + (buf) * 2 * BUFW * 4; \
    uint32_t bb = ba + BUFW * 4; \
    const char* pa = gQ + (it) * 128; \
    const char* pb = gK + (it) * 128; \
    _Pragma("unroll") \
    for (int j = 0; j < 4; ++j) { \
        cp16(ba + so + 16 * j, pa + 16 * j); \
        cp16(bb + so + 16 * j, pb + 16 * j); \
    } \
    cp_commit(); \
} while (0)

        QK_STAGE(0, 0);
        for (int it = 0; it < 16; ++it) {
            const int buf = it & 1;
            cp_wait0();
            __syncthreads();
            if (it + 1 < 16) QK_STAGE(buf ^ 1, it + 1);
            const uint32_t* bA = qkb + buf * 2 * BUFW;
            const uint32_t* bB = bA + BUFW;
#pragma unroll
            for (int kk = 0; kk < 32; kk += 8) {
                uint32_t af[2][4], bf[8][2];
#pragma unroll
                for (int mt = 0; mt < 2; ++mt) {
                    const int m = wm * 32 + mt * 16 + r;
                    af[mt][0] = bA[m * ST + kk + c];
                    af[mt][1] = bA[(m + 8) * ST + kk + c];
                    af[mt][2] = bA[m * ST + kk + c + 4];
                    af[mt][3] = bA[(m + 8) * ST + kk + c + 4];
                }
#pragma unroll
                for (int nt = 0; nt < 8; ++nt) {
                    const int n = wn * 64 + nt * 8 + r;
                    bf[nt][0] = bB[n * ST + kk + c];
                    bf[nt][1] = bB[n * ST + kk + c + 4];
                }
#pragma unroll
                for (int mt = 0; mt < 2; ++mt)
#pragma unroll
                    for (int nt = 0; nt < 8; ++nt)
                        mma_tf32(acc[mt][nt], af[mt], bf[nt]);
            }
        }
        __syncthreads();
#pragma unroll
        for (int mt = 0; mt < 2; ++mt)
#pragma unroll
            for (int nt = 0; nt < 8; ++nt) {
                const int srow = wm * 32 + mt * 16 + r;
                const int col = wn * 64 + nt * 8 + 2 * c;
                *(float2*)&sc[srow * SC_ST + col] =
                    make_float2(acc[mt][nt][0] * scale, acc[mt][nt][1] * scale);
                *(float2*)&sc[(srow + 8) * SC_ST + col] =
                    make_float2(acc[mt][nt][2] * scale, acc[mt][nt][3] * scale);
            }
        __syncthreads();
    }

    // ============ Step 2: row softmax -> tf32 probs ============
    {
        for (int row = wid * 16; row < wid * 16 + 16; ++row) {
            float4 v = *(float4*)&sc[row * SC_ST + lane * 4];
            float mx = fmaxf(fmaxf(v.x, v.y), fmaxf(v.z, v.w));
#pragma unroll
            for (int off = 16; off >= 1; off >>= 1)
                mx = fmaxf(mx, __shfl_xor_sync(0xFFFFFFFFu, mx, off));
            float4 e;
            e.x = __expf(v.x - mx); e.y = __expf(v.y - mx);
            e.z = __expf(v.z - mx); e.w = __expf(v.w - mx);
            float s = e.x + e.y + e.z + e.w;
#pragma unroll
            for (int off = 16; off >= 1; off >>= 1)
                s += __shfl_xor_sync(0xFFFFFFFFu, s, off);
            const float inv = 1.0f / s;
            uint4 u = make_uint4(f2tf32(e.x * inv), f2tf32(e.y * inv),
                                 f2tf32(e.z * inv), f2tf32(e.w * inv));
            *(uint4*)&sc[row * SC_ST + lane * 4] = u;
        }
        __syncthreads();
    }

    // ============ Step 3: O = attn V  (16 staged 32x128 V tiles) ============
    {
        const uint32_t* scu = (const uint32_t*)sc;
        uint32_t* sV = qkb;                      // reuse staging region
        const int vrow = tid >> 3;               // 0..31
        const int vcol = (tid & 7) * 16;         // 0..112
        const uint32_t svb = smem_u32(sV);
        const uint32_t vso = (vrow * V_ST + vcol) * 4;

#define V_STAGE(buf, vi) do { \
    const char* pv = (const char*)(g_v + \
        (size_t)(t0 + (((vi) & 3) << 5) + vrow) * DD + (((vi) >> 2) << 7) + vcol); \
    uint32_t bv_ = svb + (buf) * (32 * V_ST * 4); \
    _Pragma("unroll") \
    for (int j = 0; j < 4; ++j) cp16(bv_ + vso + 16 * j, pv + 16 * j); \
    cp_commit(); \
} while (0)

        float acc[2][8][4];
#pragma unroll
        for (int i = 0; i < 2; ++i)
#pragma unroll
            for (int j = 0; j < 8; ++j)
#pragma unroll
                for (int q = 0; q < 4; ++q) acc[i][j][q] = 0.f;

        V_STAGE(0, 0);
        for (int vi = 0; vi < 16; ++vi) {
            const int buf = vi & 1;
            const int k0 = (vi & 3) * 32;
            const int dc = (vi >> 2) * 128;
            cp_wait0();
            __syncthreads();
            if (vi + 1 < 16) V_STAGE(buf ^ 1, vi + 1);
            const uint32_t* bV = sV + buf * 32 * V_ST;
#pragma unroll
            for (int kk = 0; kk < 32; kk += 8) {
                uint32_t af[2][4], bf[8][2];
#pragma unroll
                for (int mt = 0; mt < 2; ++mt) {
                    const int m = wm * 32 + mt * 16 + r;
                    const int kb = k0 + kk + c;
                    af[mt][0] = scu[m * SC_ST + kb];
                    af[mt][1] = scu[(m + 8) * SC_ST + kb];
                    af[mt][2] = scu[m * SC_ST + kb + 4];
                    af[mt][3] = scu[(m + 8) * SC_ST + kb + 4];
                }
#pragma unroll
                for (int nt = 0; nt < 8; ++nt) {
                    const int n = wn * 64 + nt * 8 + r;
                    bf[nt][0] = bV[(kk + c) * V_ST + n];
                    bf[nt][1] = bV[(kk + c + 4) * V_ST + n];
                }
#pragma unroll
                for (int mt = 0; mt < 2; ++mt)
#pragma unroll
                    for (int nt = 0; nt < 8; ++nt)
                        mma_tf32(acc[mt][nt], af[mt], bf[nt]);
            }
            if ((vi & 3) == 3) {
                // store this dc chunk, reset accumulators
#pragma unroll
                for (int mt = 0; mt < 2; ++mt)
#pragma unroll
                    for (int nt = 0; nt < 8; ++nt) {
                        const int orow = t0 + wm * 32 + mt * 16 + r;
                        const int col = dc + wn * 64 + nt * 8 + 2 * c;
                        *(float2*)(out + (size_t)orow * DD + col) =
                            make_float2(acc[mt][nt][0], acc[mt][nt][1]);
                        *(float2*)(out + (size_t)(orow + 8) * DD + col) =
                            make_float2(acc[mt][nt][2], acc[mt][nt][3]);
#pragma unroll
                        for (int q = 0; q < 4; ++q) acc[mt][nt][q] = 0.f;
                    }
            }
        }
    }
}

// ---------------------------------------------------------------------------
// Launch
// ---------------------------------------------------------------------------
extern "C" void kernel_launch(void* const* d_in, const int* in_sizes, int n_in,
                              void* d_out, int out_size)
{
    const float* x  = (const float*)d_in[0];
    const float* Wq = (const float*)d_in[1];
    const float* bq = (const float*)d_in[2];
    const float* Wk = (const float*)d_in[3];
    const float* bk = (const float*)d_in[4];
    const float* Wv = (const float*)d_in[5];
    const float* bv = (const float*)d_in[6];
    float* out = (float*)d_out;

    cudaFuncSetAttribute(qkv_tc,
                         cudaFuncAttributeMaxDynamicSharedMemorySize,
                         QKV_SMEM_BYTES);
    cudaFuncSetAttribute(attn_tc,
                         cudaFuncAttributeMaxDynamicSharedMemorySize,
                         ATTN_SMEM_BYTES);

    // Prep: gather + tf32-round x and W  (4,390,912 quads / 256 = 17152 blocks)
    prep_kernel<<<17152, 256>>>(x, Wq, Wk, Wv);

    // QKV projection
    dim3 g1(DD / 128, TT / 128, 3);
    qkv_tc<<<g1, 256, QKV_SMEM_BYTES>>>(bq, bk, bv);

    // Per-segment attention
    attn_tc<<<BB * NSEG, 256, ATTN_SMEM_BYTES>>>(out);
}

// round 5
// speedup vs baseline: 4.6690x; 1.9027x over previous
#include <cuda_runtime.h>
#include <cuda_fp16.h>
#include <math.h>
#include <cstdint>

// Problem constants
#define BB   4
#define SS   16384
#define DD   512
#define SEG  256
#define LL   128
#define NSEG 64
#define TT   (BB * NSEG * LL)   // 32768 dilated tokens

// Device scratch (half precision operands)
static __device__ __half g_xd[(size_t)TT * DD];
static __device__ __half g_wh[3 * DD * DD];
static __device__ __half g_q[(size_t)TT * DD];
static __device__ __half g_k[(size_t)TT * DD];
static __device__ __half g_v[(size_t)TT * DD];

// ---------------------------------------------------------------------------
// Helpers
// ---------------------------------------------------------------------------
__device__ __forceinline__ void mma_f16(float d[4], const uint32_t a[4],
                                        const uint32_t b[2]) {
    asm volatile(
        "mma.sync.aligned.m16n8k16.row.col.f32.f16.f16.f32 "
        "{%0,%1,%2,%3}, {%4,%5,%6,%7}, {%8,%9}, {%0,%1,%2,%3};\n"
        : "+f"(d[0]), "+f"(d[1]), "+f"(d[2]), "+f"(d[3])
        : "r"(a[0]), "r"(a[1]), "r"(a[2]), "r"(a[3]), "r"(b[0]), "r"(b[1]));
}
__device__ __forceinline__ void ldm_x4(uint32_t& r0, uint32_t& r1,
                                       uint32_t& r2, uint32_t& r3, uint32_t a) {
    asm volatile("ldmatrix.sync.aligned.m8n8.x4.shared.b16 {%0,%1,%2,%3}, [%4];"
                 : "=r"(r0), "=r"(r1), "=r"(r2), "=r"(r3) : "r"(a));
}
__device__ __forceinline__ void ldm_x4t(uint32_t& r0, uint32_t& r1,
                                        uint32_t& r2, uint32_t& r3, uint32_t a) {
    asm volatile("ldmatrix.sync.aligned.m8n8.x4.trans.shared.b16 {%0,%1,%2,%3}, [%4];"
                 : "=r"(r0), "=r"(r1), "=r"(r2), "=r"(r3) : "r"(a));
}
__device__ __forceinline__ uint32_t smem_u32(const void* p) {
    uint32_t a;
    asm("{ .reg .u64 t; cvta.to.shared.u64 t, %1; cvt.u32.u64 %0, t; }"
        : "=r"(a) : "l"(p));
    return a;
}
__device__ __forceinline__ void cp16(uint32_t dst, const void* src) {
    asm volatile("cp.async.cg.shared.global [%0], [%1], 16;"
                 :: "r"(dst), "l"(src));
}
__device__ __forceinline__ void cp_commit() {
    asm volatile("cp.async.commit_group;" ::: "memory");
}
__device__ __forceinline__ void cp_wait0() {
    asm volatile("cp.async.wait_group 0;" ::: "memory");
}

// ---------------------------------------------------------------------------
// Prep: gather dilated rows of x and convert x, W to half.
// ---------------------------------------------------------------------------
#define XQ ((size_t)TT * DD / 4)          // 4,194,304 quads
#define WQ ((size_t)3 * DD * DD / 4)      //   196,608 quads

__global__ __launch_bounds__(256)
void prep_kernel(const float* __restrict__ x,
                 const float* __restrict__ Wq,
                 const float* __restrict__ Wk,
                 const float* __restrict__ Wv)
{
    const size_t qi = (size_t)blockIdx.x * blockDim.x + threadIdx.x;
    if (qi < XQ) {
        const int t = (int)(qi >> 7);
        const int d = ((int)qi & 127) << 2;
        const int b_ = t >> 13, n_ = (t >> 7) & 63, l_ = t & 127;
        float4 v = *(const float4*)(x + ((size_t)(b_ * SS + n_ * SEG + l_ * 2)) * DD + d);
        __half2 h0 = __floats2half2_rn(v.x, v.y);
        __half2 h1 = __floats2half2_rn(v.z, v.w);
        *(uint2*)(g_xd + (size_t)t * DD + d) =
            make_uint2(*(uint32_t*)&h0, *(uint32_t*)&h1);
    } else {
        const size_t wi = qi - XQ;
        if (wi < WQ) {
            const int m = (int)(wi >> 16);
            const float* W = (m == 0) ? Wq : ((m == 1) ? Wk : Wv);
            const int off = ((int)wi & 65535) << 2;
            float4 v = *(const float4*)(W + off);
            __half2 h0 = __floats2half2_rn(v.x, v.y);
            __half2 h1 = __floats2half2_rn(v.z, v.w);
            *(uint2*)(g_wh + (size_t)m * DD * DD + off) =
                make_uint2(*(uint32_t*)&h0, *(uint32_t*)&h1);
        }
    }
}

// ---------------------------------------------------------------------------
// QKV projection: 128M x 128N, BK=64 halves, double-buffered cp.async,
// ldmatrix fragments, fp16 mma m16n8k16. 8 warps (4M x 2N).
// Row stride 72 halves (144B): ldmatrix phases conflict-free.
// ---------------------------------------------------------------------------
#define AST   72                     // halves per staged row
#define TILEB (128 * AST * 2)        // 18432 bytes per tile
#define QKV_SMEM_BYTES (4 * TILEB)   // 73728

__global__ __launch_bounds__(256, 2)
void qkv_tc(const float* __restrict__ bq, const float* __restrict__ bk,
            const float* __restrict__ bv)
{
    extern __shared__ char smem[];
    const uint32_t sb = smem_u32(smem);
    const int tid = threadIdx.x;
    const int lane = tid & 31, wid = tid >> 5;
    const int wm = wid >> 1, wn = wid & 1;
    const int r = lane >> 2, c = lane & 3;
    const int m0 = blockIdx.y * 128, n0 = blockIdx.x * 128, z = blockIdx.z;

    const __half* A  = g_xd + (size_t)m0 * DD;
    const __half* Bm = g_wh + (size_t)z * DD * DD + (size_t)n0 * DD;
    const float* bias = (z == 0) ? bq : ((z == 1) ? bk : bv);
    __half* out = (z == 0) ? g_q : ((z == 1) ? g_k : g_v);

    // staging: 2 threads per row, 64B each
    const int row = tid >> 1, hoff = (tid & 1) * 32;
    const __half* gA = A + (size_t)row * DD + hoff;
    const __half* gB = Bm + (size_t)row * DD + hoff;
    const uint32_t so = (row * AST + hoff) * 2;

    // ldmatrix lane offsets
    const int lra = (lane & 7) + ((lane >> 3) & 1) * 8;
    const int lca = (lane >> 4) * 8;
    const int lrb = (lane & 7) + (lane >> 4) * 8;
    const int lcb = ((lane >> 3) & 1) * 8;
    uint32_t aoff[2], boff[4];
#pragma unroll
    for (int mt = 0; mt < 2; ++mt)
        aoff[mt] = ((wm * 32 + mt * 16 + lra) * AST + lca) * 2;
#pragma unroll
    for (int p = 0; p < 4; ++p)
        boff[p] = ((wn * 64 + p * 16 + lrb) * AST + lcb) * 2;

    float acc[2][8][4];
#pragma unroll
    for (int i = 0; i < 2; ++i)
#pragma unroll
        for (int j = 0; j < 8; ++j)
#pragma unroll
            for (int q = 0; q < 4; ++q) acc[i][j][q] = 0.f;

#define QKV_STAGE(buf, it) do { \
    uint32_t da = sb + (buf) * 2 * TILEB + so; \
    uint32_t db = da + TILEB; \
    const __half* pa = gA + (it) * 64; \
    const __half* pb = gB + (it) * 64; \
    _Pragma("unroll") \
    for (int j = 0; j < 4; ++j) { \
        cp16(da + 16 * j, pa + 8 * j); \
        cp16(db + 16 * j, pb + 8 * j); \
    } \
    cp_commit(); \
} while (0)

    QKV_STAGE(0, 0);
    for (int it = 0; it < 8; ++it) {
        const int buf = it & 1;
        cp_wait0();
        __syncthreads();
        if (it + 1 < 8) QKV_STAGE(buf ^ 1, it + 1);
        const uint32_t bA = sb + buf * 2 * TILEB;
        const uint32_t bB = bA + TILEB;
#pragma unroll
        for (int kk = 0; kk < 64; kk += 16) {
            uint32_t af[2][4], bf[8][2];
#pragma unroll
            for (int mt = 0; mt < 2; ++mt)
                ldm_x4(af[mt][0], af[mt][1], af[mt][2], af[mt][3],
                       bA + aoff[mt] + kk * 2);
#pragma unroll
            for (int p = 0; p < 4; ++p)
                ldm_x4(bf[2 * p][0], bf[2 * p][1], bf[2 * p + 1][0],
                       bf[2 * p + 1][1], bB + boff[p] + kk * 2);
#pragma unroll
            for (int mt = 0; mt < 2; ++mt)
#pragma unroll
                for (int nt = 0; nt < 8; ++nt)
                    mma_f16(acc[mt][nt], af[mt], bf[nt]);
        }
    }

    // Epilogue: bias add (fp32), store half2
#pragma unroll
    for (int mt = 0; mt < 2; ++mt)
#pragma unroll
        for (int nt = 0; nt < 8; ++nt) {
            const int orow = m0 + wm * 32 + mt * 16 + r;
            const int col = n0 + wn * 64 + nt * 8 + 2 * c;
            const float b0 = bias[col], b1 = bias[col + 1];
            __half2 h0 = __floats2half2_rn(acc[mt][nt][0] + b0, acc[mt][nt][1] + b1);
            __half2 h1 = __floats2half2_rn(acc[mt][nt][2] + b0, acc[mt][nt][3] + b1);
            *(__half2*)(out + (size_t)orow * DD + col) = h0;
            *(__half2*)(out + (size_t)(orow + 8) * DD + col) = h1;
        }
}

// ---------------------------------------------------------------------------
// Attention: one CTA per segment.
// SMEM: [staging 73728][scores fp32 128x132 = 67584][probs half 128x136 = 34816]
// ---------------------------------------------------------------------------
#define OFF_SCF 73728
#define OFF_PRB (OFF_SCF + 128 * 132 * 4)
#define ATTN_SMEM_BYTES (OFF_PRB + 128 * 136 * 2)   // 176128
#define PST 136
#define VTILEB (32 * PST * 2)     // 8704 bytes per V buffer

__global__ __launch_bounds__(256, 1)
void attn_tc(float* __restrict__ out)
{
    extern __shared__ char smem[];
    const uint32_t sb = smem_u32(smem);
    float*  scf   = (float*)(smem + OFF_SCF);
    __half* probs = (__half*)(smem + OFF_PRB);

    const int seg = blockIdx.x;
    const int t0  = seg * LL;
    const int tid = threadIdx.x;
    const int lane = tid & 31, wid = tid >> 5;
    const int wm = wid >> 1, wn = wid & 1;
    const int r = lane >> 2, c = lane & 3;
    const float scale = 0.044194173824159216f;   // 1/sqrt(512)

    const int lra = (lane & 7) + ((lane >> 3) & 1) * 8;
    const int lca = (lane >> 4) * 8;
    const int lrb = (lane & 7) + (lane >> 4) * 8;
    const int lcb = ((lane >> 3) & 1) * 8;

    // ============ Step 1: scores = Q K^T * scale ============
    {
        const int row = tid >> 1, hoff = (tid & 1) * 32;
        const __half* gQ = g_q + (size_t)(t0 + row) * DD + hoff;
        const __half* gK = g_k + (size_t)(t0 + row) * DD + hoff;
        const uint32_t so = (row * AST + hoff) * 2;

        uint32_t aoff[2], boff[4];
#pragma unroll
        for (int mt = 0; mt < 2; ++mt)
            aoff[mt] = ((wm * 32 + mt * 16 + lra) * AST + lca) * 2;
#pragma unroll
        for (int p = 0; p < 4; ++p)
            boff[p] = ((wn * 64 + p * 16 + lrb) * AST + lcb) * 2;

        float acc[2][8][4];
#pragma unroll
        for (int i = 0; i < 2; ++i)
#pragma unroll
            for (int j = 0; j < 8; ++j)
#pragma unroll
                for (int q = 0; q < 4; ++q) acc[i][j][q] = 0.f;

#define QK_STAGE(buf, it) do { \
    uint32_t da = sb + (buf) * 2 * TILEB + so; \
    uint32_t db = da + TILEB; \
    const __half* pa = gQ + (it) * 64; \
    const __half* pb = gK + (it) * 64; \
    _Pragma("unroll") \
    for (int j = 0; j < 4; ++j) { \
        cp16(da + 16 * j, pa + 8 * j); \
        cp16(db + 16 * j, pb + 8 * j); \
    } \
    cp_commit(); \
} while (0)

        QK_STAGE(0, 0);
        for (int it = 0; it < 8; ++it) {
            const int buf = it & 1;
            cp_wait0();
            __syncthreads();
            if (it + 1 < 8) QK_STAGE(buf ^ 1, it + 1);
            const uint32_t bA = sb + buf * 2 * TILEB;
            const uint32_t bB = bA + TILEB;
#pragma unroll
            for (int kk = 0; kk < 64; kk += 16) {
                uint32_t af[2][4], bf[8][2];
#pragma unroll
                for (int mt = 0; mt < 2; ++mt)
                    ldm_x4(af[mt][0], af[mt][1], af[mt][2], af[mt][3],
                           bA + aoff[mt] + kk * 2);
#pragma unroll
                for (int p = 0; p < 4; ++p)
                    ldm_x4(bf[2 * p][0], bf[2 * p][1], bf[2 * p + 1][0],
                           bf[2 * p + 1][1], bB + boff[p] + kk * 2);
#pragma unroll
                for (int mt = 0; mt < 2; ++mt)
#pragma unroll
                    for (int nt = 0; nt < 8; ++nt)
                        mma_f16(acc[mt][nt], af[mt], bf[nt]);
            }
        }
        __syncthreads();
#pragma unroll
        for (int mt = 0; mt < 2; ++mt)
#pragma unroll
            for (int nt = 0; nt < 8; ++nt) {
                const int srow = wm * 32 + mt * 16 + r;
                const int col = wn * 64 + nt * 8 + 2 * c;
                *(float2*)&scf[srow * 132 + col] =
                    make_float2(acc[mt][nt][0] * scale, acc[mt][nt][1] * scale);
                *(float2*)&scf[(srow + 8) * 132 + col] =
                    make_float2(acc[mt][nt][2] * scale, acc[mt][nt][3] * scale);
            }
        __syncthreads();
    }

    // ============ Step 2: row softmax (fp32) -> probs (half) ============
    {
        for (int row = wid * 16; row < wid * 16 + 16; ++row) {
            float4 v = *(float4*)&scf[row * 132 + lane * 4];
            float mx = fmaxf(fmaxf(v.x, v.y), fmaxf(v.z, v.w));
#pragma unroll
            for (int off = 16; off >= 1; off >>= 1)
                mx = fmaxf(mx, __shfl_xor_sync(0xFFFFFFFFu, mx, off));
            float4 e;
            e.x = __expf(v.x - mx); e.y = __expf(v.y - mx);
            e.z = __expf(v.z - mx); e.w = __expf(v.w - mx);
            float s = e.x + e.y + e.z + e.w;
#pragma unroll
            for (int off = 16; off >= 1; off >>= 1)
                s += __shfl_xor_sync(0xFFFFFFFFu, s, off);
            const float inv = 1.0f / s;
            __half2 h0 = __floats2half2_rn(e.x * inv, e.y * inv);
            __half2 h1 = __floats2half2_rn(e.z * inv, e.w * inv);
            *(uint2*)(probs + row * PST + lane * 4) =
                make_uint2(*(uint32_t*)&h0, *(uint32_t*)&h1);
        }
        __syncthreads();
    }

    // ============ Step 3: O = attn V  (16 staged 32k x 128n V tiles) ============
    {
        const int vrow = tid >> 3;               // 0..31
        const int vh   = (tid & 7) * 16;         // half offset within row
        const uint32_t vso = (vrow * PST + vh) * 2;

        uint32_t poff[2], voff[4];
#pragma unroll
        for (int mt = 0; mt < 2; ++mt)
            poff[mt] = (uint32_t)OFF_PRB + ((wm * 32 + mt * 16 + lra) * PST + lca) * 2;
#pragma unroll
        for (int p = 0; p < 4; ++p)
            voff[p] = (lra * PST + wn * 64 + p * 16 + (lane >> 4) * 8) * 2;

#define V_STAGE(buf, vi) do { \
    const __half* pv = g_v + \
        (size_t)(t0 + (((vi) & 3) << 5) + vrow) * DD + (((vi) >> 2) << 7) + vh; \
    uint32_t dv = sb + (buf) * VTILEB + vso; \
    cp16(dv, pv); \
    cp16(dv + 16, pv + 8); \
    cp_commit(); \
} while (0)

        float acc[2][8][4];
#pragma unroll
        for (int i = 0; i < 2; ++i)
#pragma unroll
            for (int j = 0; j < 8; ++j)
#pragma unroll
                for (int q = 0; q < 4; ++q) acc[i][j][q] = 0.f;

        V_STAGE(0, 0);
        for (int vi = 0; vi < 16; ++vi) {
            const int buf = vi & 1;
            const int k0 = (vi & 3) * 32;
            const int dc = (vi >> 2) * 128;
            cp_wait0();
            __syncthreads();
            if (vi + 1 < 16) V_STAGE(buf ^ 1, vi + 1);
            const uint32_t bV = sb + buf * VTILEB;
#pragma unroll
            for (int kk = 0; kk < 32; kk += 16) {
                uint32_t af[2][4], bf[8][2];
#pragma unroll
                for (int mt = 0; mt < 2; ++mt)
                    ldm_x4(af[mt][0], af[mt][1], af[mt][2], af[mt][3],
                           sb + poff[mt] + (k0 + kk) * 2);
#pragma unroll
                for (int p = 0; p < 4; ++p)
                    ldm_x4t(bf[2 * p][0], bf[2 * p][1], bf[2 * p + 1][0],
                            bf[2 * p + 1][1], bV + voff[p] + kk * PST * 2);
#pragma unroll
                for (int mt = 0; mt < 2; ++mt)
#pragma unroll
                    for (int nt = 0; nt < 8; ++nt)
                        mma_f16(acc[mt][nt], af[mt], bf[nt]);
            }
            if ((vi & 3) == 3) {
#pragma unroll
                for (int mt = 0; mt < 2; ++mt)
#pragma unroll
                    for (int nt = 0; nt < 8; ++nt) {
                        const int orow = t0 + wm * 32 + mt * 16 + r;
                        const int col = dc + wn * 64 + nt * 8 + 2 * c;
                        *(float2*)(out + (size_t)orow * DD + col) =
                            make_float2(acc[mt][nt][0], acc[mt][nt][1]);
                        *(float2*)(out + (size_t)(orow + 8) * DD + col) =
                            make_float2(acc[mt][nt][2], acc[mt][nt][3]);
#pragma unroll
                        for (int q = 0; q < 4; ++q) acc[mt][nt][q] = 0.f;
                    }
            }
        }
    }
}

// ---------------------------------------------------------------------------
// Launch
// ---------------------------------------------------------------------------
extern "C" void kernel_launch(void* const* d_in, const int* in_sizes, int n_in,
                              void* d_out, int out_size)
{
    const float* x  = (const float*)d_in[0];
    const float* Wq = (const float*)d_in[1];
    const float* bq = (const float*)d_in[2];
    const float* Wk = (const float*)d_in[3];
    const float* bk = (const float*)d_in[4];
    const float* Wv = (const float*)d_in[5];
    const float* bv = (const float*)d_in[6];
    float* out = (float*)d_out;

    cudaFuncSetAttribute(qkv_tc,
                         cudaFuncAttributeMaxDynamicSharedMemorySize,
                         QKV_SMEM_BYTES);
    cudaFuncSetAttribute(attn_tc,
                         cudaFuncAttributeMaxDynamicSharedMemorySize,
                         ATTN_SMEM_BYTES);

    prep_kernel<<<17152, 256>>>(x, Wq, Wk, Wv);

    dim3 g1(DD / 128, TT / 128, 3);
    qkv_tc<<<g1, 256, QKV_SMEM_BYTES>>>(bq, bk, bv);

    attn_tc<<<BB * NSEG, 256, ATTN_SMEM_BYTES>>>(out);
}

// round 7
// speedup vs baseline: 5.2785x; 1.1305x over previous
#include <cuda_runtime.h>
#include <cuda_fp16.h>
#include <math.h>
#include <cstdint>

// Problem constants
#define BB   4
#define SS   16384
#define DD   512
#define SEG  256
#define LL   128
#define NSEG 64
#define TT   (BB * NSEG * LL)   // 32768 dilated tokens

// Device scratch (half precision operands)
static __device__ __half g_xd[(size_t)TT * DD];
static __device__ __half g_wh[3 * DD * DD];
static __device__ __half g_q[(size_t)TT * DD];
static __device__ __half g_k[(size_t)TT * DD];
static __device__ __half g_v[(size_t)TT * DD];

// ---------------------------------------------------------------------------
// Helpers
// ---------------------------------------------------------------------------
__device__ __forceinline__ void mma_f16(float d[4], const uint32_t a[4],
                                        const uint32_t b[2]) {
    asm volatile(
        "mma.sync.aligned.m16n8k16.row.col.f32.f16.f16.f32 "
        "{%0,%1,%2,%3}, {%4,%5,%6,%7}, {%8,%9}, {%0,%1,%2,%3};\n"
        : "+f"(d[0]), "+f"(d[1]), "+f"(d[2]), "+f"(d[3])
        : "r"(a[0]), "r"(a[1]), "r"(a[2]), "r"(a[3]), "r"(b[0]), "r"(b[1]));
}
__device__ __forceinline__ void ldm_x4(uint32_t& r0, uint32_t& r1,
                                       uint32_t& r2, uint32_t& r3, uint32_t a) {
    asm volatile("ldmatrix.sync.aligned.m8n8.x4.shared.b16 {%0,%1,%2,%3}, [%4];"
                 : "=r"(r0), "=r"(r1), "=r"(r2), "=r"(r3) : "r"(a));
}
__device__ __forceinline__ void ldm_x4t(uint32_t& r0, uint32_t& r1,
                                        uint32_t& r2, uint32_t& r3, uint32_t a) {
    asm volatile("ldmatrix.sync.aligned.m8n8.x4.trans.shared.b16 {%0,%1,%2,%3}, [%4];"
                 : "=r"(r0), "=r"(r1), "=r"(r2), "=r"(r3) : "r"(a));
}
__device__ __forceinline__ uint32_t smem_u32(const void* p) {
    uint32_t a;
    asm("{ .reg .u64 t; cvta.to.shared.u64 t, %1; cvt.u32.u64 %0, t; }"
        : "=r"(a) : "l"(p));
    return a;
}
__device__ __forceinline__ void cp16(uint32_t dst, const void* src) {
    asm volatile("cp.async.cg.shared.global [%0], [%1], 16;"
                 :: "r"(dst), "l"(src));
}
__device__ __forceinline__ void cp_commit() {
    asm volatile("cp.async.commit_group;" ::: "memory");
}
__device__ __forceinline__ void cp_wait1() {
    asm volatile("cp.async.wait_group 1;" ::: "memory");
}
__device__ __forceinline__ void cp_wait0() {
    asm volatile("cp.async.wait_group 0;" ::: "memory");
}

// ---------------------------------------------------------------------------
// Prep: gather dilated rows of x and convert x, W to half.
// ---------------------------------------------------------------------------
#define XQ ((size_t)TT * DD / 4)
#define WQ ((size_t)3 * DD * DD / 4)

__global__ __launch_bounds__(256)
void prep_kernel(const float* __restrict__ x,
                 const float* __restrict__ Wq,
                 const float* __restrict__ Wk,
                 const float* __restrict__ Wv)
{
    const size_t qi = (size_t)blockIdx.x * blockDim.x + threadIdx.x;
    if (qi < XQ) {
        const int t = (int)(qi >> 7);
        const int d = ((int)qi & 127) << 2;
        const int b_ = t >> 13, n_ = (t >> 7) & 63, l_ = t & 127;
        float4 v = *(const float4*)(x + ((size_t)(b_ * SS + n_ * SEG + l_ * 2)) * DD + d);
        __half2 h0 = __floats2half2_rn(v.x, v.y);
        __half2 h1 = __floats2half2_rn(v.z, v.w);
        *(uint2*)(g_xd + (size_t)t * DD + d) =
            make_uint2(*(uint32_t*)&h0, *(uint32_t*)&h1);
    } else {
        const size_t wi = qi - XQ;
        if (wi < WQ) {
            const int m = (int)(wi >> 16);
            const float* W = (m == 0) ? Wq : ((m == 1) ? Wk : Wv);
            const int off = ((int)wi & 65535) << 2;
            float4 v = *(const float4*)(W + off);
            __half2 h0 = __floats2half2_rn(v.x, v.y);
            __half2 h1 = __floats2half2_rn(v.z, v.w);
            *(uint2*)(g_wh + (size_t)m * DD * DD + off) =
                make_uint2(*(uint32_t*)&h0, *(uint32_t*)&h1);
        }
    }
}

// ---------------------------------------------------------------------------
// QKV projection: 128M x 128N, BK=64 halves, 3-stage cp.async pipeline
// (2 groups in flight), ldmatrix fragments, fp16 mma. 8 warps (4M x 2N).
// ---------------------------------------------------------------------------
#define AST   72
#define TILEB (128 * AST * 2)            // 18432 bytes per tile
#define QKV_SMEM_BYTES (6 * TILEB)       // 110592 (3 stages x A,B)

__global__ __launch_bounds__(256, 2)
void qkv_tc(const float* __restrict__ bq, const float* __restrict__ bk,
            const float* __restrict__ bv)
{
    extern __shared__ char smem[];
    const uint32_t sb = smem_u32(smem);
    const int tid = threadIdx.x;
    const int lane = tid & 31, wid = tid >> 5;
    const int wm = wid >> 1, wn = wid & 1;
    const int r = lane >> 2, c = lane & 3;
    const int m0 = blockIdx.y * 128, n0 = blockIdx.x * 128, z = blockIdx.z;

    const __half* A  = g_xd + (size_t)m0 * DD;
    const __half* Bm = g_wh + (size_t)z * DD * DD + (size_t)n0 * DD;
    const float* bias = (z == 0) ? bq : ((z == 1) ? bk : bv);
    __half* out = (z == 0) ? g_q : ((z == 1) ? g_k : g_v);

    const int row = tid >> 1, hoff = (tid & 1) * 32;
    const __half* gA = A + (size_t)row * DD + hoff;
    const __half* gB = Bm + (size_t)row * DD + hoff;
    const uint32_t so = (row * AST + hoff) * 2;

    const int lra = (lane & 7) + ((lane >> 3) & 1) * 8;
    const int lca = (lane >> 4) * 8;
    const int lrb = (lane & 7) + (lane >> 4) * 8;
    const int lcb = ((lane >> 3) & 1) * 8;
    uint32_t aoff[2], boff[4];
#pragma unroll
    for (int mt = 0; mt < 2; ++mt)
        aoff[mt] = ((wm * 32 + mt * 16 + lra) * AST + lca) * 2;
#pragma unroll
    for (int p = 0; p < 4; ++p)
        boff[p] = ((wn * 64 + p * 16 + lrb) * AST + lcb) * 2;

    float acc[2][8][4];
#pragma unroll
    for (int i = 0; i < 2; ++i)
#pragma unroll
        for (int j = 0; j < 8; ++j)
#pragma unroll
            for (int q = 0; q < 4; ++q) acc[i][j][q] = 0.f;

#define QKV_STAGE(buf, it) do { \
    uint32_t da = sb + (buf) * 2 * TILEB + so; \
    uint32_t db = da + TILEB; \
    const __half* pa = gA + (it) * 64; \
    const __half* pb = gB + (it) * 64; \
    _Pragma("unroll") \
    for (int j = 0; j < 4; ++j) { \
        cp16(da + 16 * j, pa + 8 * j); \
        cp16(db + 16 * j, pb + 8 * j); \
    } \
    cp_commit(); \
} while (0)

    QKV_STAGE(0, 0);
    QKV_STAGE(1, 1);
#pragma unroll
    for (int it = 0; it < 8; ++it) {
        const int buf = it % 3;
        // Last iteration consumes the final committed group: must fully drain.
        if (it == 7) cp_wait0(); else cp_wait1();
        __syncthreads();
        if (it + 2 < 8) QKV_STAGE((it + 2) % 3, it + 2);
        const uint32_t bA = sb + buf * 2 * TILEB;
        const uint32_t bB = bA + TILEB;
#pragma unroll
        for (int kk = 0; kk < 64; kk += 16) {
            uint32_t af[2][4], bf[8][2];
#pragma unroll
            for (int mt = 0; mt < 2; ++mt)
                ldm_x4(af[mt][0], af[mt][1], af[mt][2], af[mt][3],
                       bA + aoff[mt] + kk * 2);
#pragma unroll
            for (int p = 0; p < 4; ++p)
                ldm_x4(bf[2 * p][0], bf[2 * p][1], bf[2 * p + 1][0],
                       bf[2 * p + 1][1], bB + boff[p] + kk * 2);
#pragma unroll
            for (int mt = 0; mt < 2; ++mt)
#pragma unroll
                for (int nt = 0; nt < 8; ++nt)
                    mma_f16(acc[mt][nt], af[mt], bf[nt]);
        }
    }

#pragma unroll
    for (int mt = 0; mt < 2; ++mt)
#pragma unroll
        for (int nt = 0; nt < 8; ++nt) {
            const int orow = m0 + wm * 32 + mt * 16 + r;
            const int col = n0 + wn * 64 + nt * 8 + 2 * c;
            const float b0 = bias[col], b1 = bias[col + 1];
            __half2 h0 = __floats2half2_rn(acc[mt][nt][0] + b0, acc[mt][nt][1] + b1);
            __half2 h1 = __floats2half2_rn(acc[mt][nt][2] + b0, acc[mt][nt][3] + b1);
            *(__half2*)(out + (size_t)orow * DD + col) = h0;
            *(__half2*)(out + (size_t)(orow + 8) * DD + col) = h1;
        }
}

// ---------------------------------------------------------------------------
// Attention: one CTA per segment, 2 CTAs/SM.
// Register softmax: no fp32 score array; probs written half direct from frags.
// SMEM: [staging 73728][probs 128x136 half = 34816][red 2048] = 110592
// ---------------------------------------------------------------------------
#define OFF_PRB 73728
#define OFF_RED (OFF_PRB + 128 * 136 * 2)
#define ATTN_SMEM_BYTES (OFF_RED + 2048)    // 110592
#define PST 136
#define VTILEB (32 * PST * 2)               // 8704 bytes per V buffer

__global__ __launch_bounds__(256, 2)
void attn_tc(float* __restrict__ out)
{
    extern __shared__ char smem[];
    const uint32_t sb = smem_u32(smem);
    __half* probs = (__half*)(smem + OFF_PRB);
    float*  redM  = (float*)(smem + OFF_RED);         // [128][2]
    float*  redS  = redM + 256;                       // [128][2]

    const int seg = blockIdx.x;
    const int t0  = seg * LL;
    const int tid = threadIdx.x;
    const int lane = tid & 31, wid = tid >> 5;
    const int wm = wid >> 1, wn = wid & 1;
    const int r = lane >> 2, c = lane & 3;
    const float scale = 0.044194173824159216f;   // 1/sqrt(512)

    const int lra = (lane & 7) + ((lane >> 3) & 1) * 8;
    const int lca = (lane >> 4) * 8;
    const int lrb = (lane & 7) + (lane >> 4) * 8;
    const int lcb = ((lane >> 3) & 1) * 8;

    // ============ Step 1: scores = Q K^T (kept in registers) ============
    float acc[2][8][4];
#pragma unroll
    for (int i = 0; i < 2; ++i)
#pragma unroll
        for (int j = 0; j < 8; ++j)
#pragma unroll
            for (int q = 0; q < 4; ++q) acc[i][j][q] = 0.f;
    {
        const int row = tid >> 1, hoff = (tid & 1) * 32;
        const __half* gQ = g_q + (size_t)(t0 + row) * DD + hoff;
        const __half* gK = g_k + (size_t)(t0 + row) * DD + hoff;
        const uint32_t so = (row * AST + hoff) * 2;

        uint32_t aoff[2], boff[4];
#pragma unroll
        for (int mt = 0; mt < 2; ++mt)
            aoff[mt] = ((wm * 32 + mt * 16 + lra) * AST + lca) * 2;
#pragma unroll
        for (int p = 0; p < 4; ++p)
            boff[p] = ((wn * 64 + p * 16 + lrb) * AST + lcb) * 2;

#define QK_STAGE(buf, it) do { \
    uint32_t da = sb + (buf) * 2 * TILEB + so; \
    uint32_t db = da + TILEB; \
    const __half* pa = gQ + (it) * 64; \
    const __half* pb = gK + (it) * 64; \
    _Pragma("unroll") \
    for (int j = 0; j < 4; ++j) { \
        cp16(da + 16 * j, pa + 8 * j); \
        cp16(db + 16 * j, pb + 8 * j); \
    } \
    cp_commit(); \
} while (0)

        QK_STAGE(0, 0);
        QK_STAGE(1, 1);
#pragma unroll
        for (int it = 0; it < 8; ++it) {
            const int buf = it % 2;                  // 2 buffers in staging
            if (it == 7) cp_wait0(); else cp_wait1();
            __syncthreads();
            const uint32_t bA = sb + buf * 2 * TILEB;
            const uint32_t bB = bA + TILEB;
#pragma unroll
            for (int kk = 0; kk < 64; kk += 16) {
                uint32_t af[2][4], bf[8][2];
#pragma unroll
                for (int mt = 0; mt < 2; ++mt)
                    ldm_x4(af[mt][0], af[mt][1], af[mt][2], af[mt][3],
                           bA + aoff[mt] + kk * 2);
#pragma unroll
                for (int p = 0; p < 4; ++p)
                    ldm_x4(bf[2 * p][0], bf[2 * p][1], bf[2 * p + 1][0],
                           bf[2 * p + 1][1], bB + boff[p] + kk * 2);
#pragma unroll
                for (int mt = 0; mt < 2; ++mt)
#pragma unroll
                    for (int nt = 0; nt < 8; ++nt)
                        mma_f16(acc[mt][nt], af[mt], bf[nt]);
            }
            if (it + 2 < 8) {
                __syncthreads();                     // buf consumed by all
                QK_STAGE(buf, it + 2);
            }
        }
    }

    // ============ Step 2: register softmax -> half probs ============
    {
#pragma unroll
        for (int mt = 0; mt < 2; ++mt)
#pragma unroll
            for (int nt = 0; nt < 8; ++nt)
#pragma unroll
                for (int q = 0; q < 4; ++q) acc[mt][nt][q] *= scale;

        // pass 1: per-row max over this warp's 64 cols
#pragma unroll
        for (int mt = 0; mt < 2; ++mt)
#pragma unroll
            for (int h = 0; h < 2; ++h) {
                float m = -1e30f;
#pragma unroll
                for (int nt = 0; nt < 8; ++nt)
                    m = fmaxf(m, fmaxf(acc[mt][nt][2 * h], acc[mt][nt][2 * h + 1]));
                m = fmaxf(m, __shfl_xor_sync(0xFFFFFFFFu, m, 1));
                m = fmaxf(m, __shfl_xor_sync(0xFFFFFFFFu, m, 2));
                if (c == 0) {
                    const int rw = wm * 32 + mt * 16 + h * 8 + r;
                    redM[rw * 2 + wn] = m;
                }
            }
        __syncthreads();

        // pass 2: exp + per-row sum
#pragma unroll
        for (int mt = 0; mt < 2; ++mt)
#pragma unroll
            for (int h = 0; h < 2; ++h) {
                const int rw = wm * 32 + mt * 16 + h * 8 + r;
                const float m = fmaxf(redM[rw * 2], redM[rw * 2 + 1]);
                float s = 0.f;
#pragma unroll
                for (int nt = 0; nt < 8; ++nt) {
                    float e0 = __expf(acc[mt][nt][2 * h] - m);
                    float e1 = __expf(acc[mt][nt][2 * h + 1] - m);
                    acc[mt][nt][2 * h] = e0;
                    acc[mt][nt][2 * h + 1] = e1;
                    s += e0 + e1;
                }
                s += __shfl_xor_sync(0xFFFFFFFFu, s, 1);
                s += __shfl_xor_sync(0xFFFFFFFFu, s, 2);
                if (c == 0) redS[rw * 2 + wn] = s;
            }
        __syncthreads();

        // pass 3: normalize, store half probs
#pragma unroll
        for (int mt = 0; mt < 2; ++mt)
#pragma unroll
            for (int h = 0; h < 2; ++h) {
                const int rw = wm * 32 + mt * 16 + h * 8 + r;
                const float inv = 1.0f / (redS[rw * 2] + redS[rw * 2 + 1]);
#pragma unroll
                for (int nt = 0; nt < 8; ++nt) {
                    __half2 hp = __floats2half2_rn(acc[mt][nt][2 * h] * inv,
                                                   acc[mt][nt][2 * h + 1] * inv);
                    *(__half2*)(probs + rw * PST + wn * 64 + nt * 8 + 2 * c) = hp;
                }
            }
        __syncthreads();
    }

    // ============ Step 3: O = attn V (3-stage V pipeline) ============
    {
        const int vrow = tid >> 3;
        const int vh   = (tid & 7) * 16;
        const uint32_t vso = (vrow * PST + vh) * 2;

        uint32_t poff[2], voff[4];
#pragma unroll
        for (int mt = 0; mt < 2; ++mt)
            poff[mt] = (uint32_t)OFF_PRB + ((wm * 32 + mt * 16 + lra) * PST + lca) * 2;
#pragma unroll
        for (int p = 0; p < 4; ++p)
            voff[p] = (lra * PST + wn * 64 + p * 16 + (lane >> 4) * 8) * 2;

#define V_STAGE(buf, vi) do { \
    const __half* pv = g_v + \
        (size_t)(t0 + (((vi) & 3) << 5) + vrow) * DD + (((vi) >> 2) << 7) + vh; \
    uint32_t dv = sb + (buf) * VTILEB + vso; \
    cp16(dv, pv); \
    cp16(dv + 16, pv + 8); \
    cp_commit(); \
} while (0)

        float oac[2][8][4];
#pragma unroll
        for (int i = 0; i < 2; ++i)
#pragma unroll
            for (int j = 0; j < 8; ++j)
#pragma unroll
                for (int q = 0; q < 4; ++q) oac[i][j][q] = 0.f;

        V_STAGE(0, 0);
        V_STAGE(1, 1);
#pragma unroll
        for (int vi = 0; vi < 16; ++vi) {
            const int buf = vi % 3;
            const int k0 = (vi & 3) * 32;
            const int dc = (vi >> 2) * 128;
            if (vi == 15) cp_wait0(); else cp_wait1();
            __syncthreads();
            if (vi + 2 < 16) V_STAGE((vi + 2) % 3, vi + 2);
            const uint32_t bV = sb + buf * VTILEB;
#pragma unroll
            for (int kk = 0; kk < 32; kk += 16) {
                uint32_t af[2][4], bf[8][2];
#pragma unroll
                for (int mt = 0; mt < 2; ++mt)
                    ldm_x4(af[mt][0], af[mt][1], af[mt][2], af[mt][3],
                           sb + poff[mt] + (k0 + kk) * 2);
#pragma unroll
                for (int p = 0; p < 4; ++p)
                    ldm_x4t(bf[2 * p][0], bf[2 * p][1], bf[2 * p + 1][0],
                            bf[2 * p + 1][1], bV + voff[p] + kk * PST * 2);
#pragma unroll
                for (int mt = 0; mt < 2; ++mt)
#pragma unroll
                    for (int nt = 0; nt < 8; ++nt)
                        mma_f16(oac[mt][nt], af[mt], bf[nt]);
            }
            if ((vi & 3) == 3) {
#pragma unroll
                for (int mt = 0; mt < 2; ++mt)
#pragma unroll
                    for (int nt = 0; nt < 8; ++nt) {
                        const int orow = t0 + wm * 32 + mt * 16 + r;
                        const int col = dc + wn * 64 + nt * 8 + 2 * c;
                        *(float2*)(out + (size_t)orow * DD + col) =
                            make_float2(oac[mt][nt][0], oac[mt][nt][1]);
                        *(float2*)(out + (size_t)(orow + 8) * DD + col) =
                            make_float2(oac[mt][nt][2], oac[mt][nt][3]);
#pragma unroll
                        for (int q = 0; q < 4; ++q) oac[mt][nt][q] = 0.f;
                    }
            }
        }
    }
}

// ---------------------------------------------------------------------------
// Launch
// ---------------------------------------------------------------------------
extern "C" void kernel_launch(void* const* d_in, const int* in_sizes, int n_in,
                              void* d_out, int out_size)
{
    const float* x  = (const float*)d_in[0];
    const float* Wq = (const float*)d_in[1];
    const float* bq = (const float*)d_in[2];
    const float* Wk = (const float*)d_in[3];
    const float* bk = (const float*)d_in[4];
    const float* Wv = (const float*)d_in[5];
    const float* bv = (const float*)d_in[6];
    float* out = (float*)d_out;

    cudaFuncSetAttribute(qkv_tc,
                         cudaFuncAttributeMaxDynamicSharedMemorySize,
                         QKV_SMEM_BYTES);
    cudaFuncSetAttribute(attn_tc,
                         cudaFuncAttributeMaxDynamicSharedMemorySize,
                         ATTN_SMEM_BYTES);

    prep_kernel<<<17152, 256>>>(x, Wq, Wk, Wv);

    dim3 g1(DD / 128, TT / 128, 3);
    qkv_tc<<<g1, 256, QKV_SMEM_BYTES>>>(bq, bk, bv);

    attn_tc<<<BB * NSEG, 256, ATTN_SMEM_BYTES>>>(out);
}